// round 15
// baseline (speedup 1.0000x reference)
#include <cuda_runtime.h>
#include <cuda_fp16.h>
#include <cuda_bf16.h>
#include <cstdint>

#define NMAX 100000
#define EMAX 1700000
#define EPS 1e-5f

// -------- scratch (static device globals; no allocation allowed) --------
__device__ __half g_h[(size_t)NMAX * 128];    // GEMM output h (fp16)
__device__ __half g_aggh[(size_t)NMAX * 128]; // layer-0 aggregation (fp16)
__device__ float g_s[NMAX];
__device__ float g_d[NMAX];
__device__ int   g_deg[NMAX];
__device__ int   g_rowptr[NMAX + 1];
__device__ int   g_cursor[NMAX];
__device__ int   g_csrc[EMAX];
__device__ int   g_bsums[256];
__device__ float g_stats0[256];
__device__ float g_stats1[256];

// ---------------------- packed f32x2 helpers ------------------------------
__device__ __forceinline__ void fma2(uint64_t& d, uint64_t a, uint64_t b) {
    asm("fma.rn.f32x2 %0, %1, %2, %3;" : "=l"(d) : "l"(a), "l"(b), "l"(d));
}
__device__ __forceinline__ uint64_t dup2(float x) {
    uint64_t r;
    asm("mov.b64 %0, {%1, %1};" : "=l"(r) : "f"(x));
    return r;
}
__device__ __forceinline__ uint64_t pack2(float x, float y) {
    uint64_t r;
    asm("mov.b64 %0, {%1, %2};" : "=l"(r) : "f"(x), "f"(y));
    return r;
}
__device__ __forceinline__ float2 unpack2(uint64_t v) {
    float2 f;
    asm("mov.b64 {%0, %1}, %2;" : "=f"(f.x), "=f"(f.y) : "l"(v));
    return f;
}

// ---------------------- bf16 split + mma helpers --------------------------
__device__ __forceinline__ void bf16_split2(float x, float y,
                                            __nv_bfloat162& hi,
                                            __nv_bfloat162& lo) {
    __nv_bfloat16 hx = __float2bfloat16_rn(x);
    __nv_bfloat16 hy = __float2bfloat16_rn(y);
    hi.x = hx; hi.y = hy;
    lo.x = __float2bfloat16_rn(x - __bfloat162float(hx));
    lo.y = __float2bfloat16_rn(y - __bfloat162float(hy));
}
// m16n8k16 bf16 MMA, fp32 accumulate (baseline PTX, sm_80+)
__device__ __forceinline__ void mma_bf16(float* c, const uint32_t* a,
                                         uint32_t b0, uint32_t b1) {
    asm("mma.sync.aligned.m16n8k16.row.col.f32.bf16.bf16.f32 "
        "{%0,%1,%2,%3}, {%4,%5,%6,%7}, {%8,%9}, {%0,%1,%2,%3};"
        : "+f"(c[0]), "+f"(c[1]), "+f"(c[2]), "+f"(c[3])
        : "r"(a[0]), "r"(a[1]), "r"(a[2]), "r"(a[3]), "r"(b0), "r"(b1));
}

// --------------------- split-bf16 tensor-core GEMM ------------------------
// AHALF: A is fp16 (8-byte loads per 4 elems); else fp32 (16-byte loads).
template <int BN, bool TRANSFORM, bool AHALF>
__global__ __launch_bounds__(256) void gemm_mma_kernel(
    int M, int K,
    const void* __restrict__ Ap,
    const float* __restrict__ B,
    __half* __restrict__ C,
    const float* __restrict__ a_s,
    const float* __restrict__ a_d,
    float* __restrict__ so, float* __restrict__ dout,
    const float* __restrict__ stats,
    const float* __restrict__ gamma,
    const float* __restrict__ beta) {
    constexpr int KC = 16;
    constexpr int K2 = KC / 2;
    constexpr int NT = BN / 16;
    __shared__ __nv_bfloat162 Ah2[K2][136], Al2[K2][136];
    __shared__ __nv_bfloat162 Bh2[K2][BN + 8], Bl2[K2][BN + 8];
    __shared__ float sscale[128], sshift[128];
    __shared__ float sS[128], sD[128];

    const int tid = threadIdx.x;
    const int warp = tid >> 5;
    const int lane = tid & 31;
    const int q = lane & 3;
    const int r8 = lane >> 2;
    const int warpRow = warp & 3;
    const int warpCol = warp >> 2;
    const int rowBase = blockIdx.x * 128;
    const int wrow = warpRow * 32;
    const int wcol = warpCol * (BN / 2);

    float acc[2][NT][4];
#pragma unroll
    for (int mt = 0; mt < 2; mt++)
#pragma unroll
        for (int nt = 0; nt < NT; nt++)
#pragma unroll
            for (int j = 0; j < 4; j++) acc[mt][nt][j] = 0.f;

    auto loadA = [&](int gr, int kb) -> float4 {
        if (gr >= M) return make_float4(0.f, 0.f, 0.f, 0.f);
        if (AHALF) {
            uint2 u = *(const uint2*)((const __half*)Ap + (size_t)gr * K + kb);
            float2 p0 = __half22float2(*(const __half2*)&u.x);
            float2 p1 = __half22float2(*(const __half2*)&u.y);
            return make_float4(p0.x, p0.y, p1.x, p1.y);
        } else {
            return *(const float4*)((const float*)Ap + (size_t)gr * K + kb);
        }
    };

    float4 ra[2];
    float4 rbE, rbO;
    const int bk2 = (BN == 128) ? (tid >> 5) : (tid >> 4);
    const int bn4 = (BN == 128) ? (tid & 31) : (tid & 15);
    const bool bAct = (BN == 128) || (tid < 128);

#pragma unroll
    for (int it = 0; it < 2; it++) {
        int idx = tid + it * 256;
        int r = idx >> 2, c4 = idx & 3;
        ra[it] = loadA(rowBase + r, c4 * 4);
    }
    if (bAct) {
        rbE = *(const float4*)(B + (size_t)(bk2 * 2) * BN + bn4 * 4);
        rbO = *(const float4*)(B + (size_t)(bk2 * 2 + 1) * BN + bn4 * 4);
    }

    if (TRANSFORM) {
        if (tid < K) {
            float invn = 1.f / (float)M;
            float mu = stats[tid] * invn;
            float var = stats[128 + tid] * invn - mu * mu;
            float sc = gamma[tid] * rsqrtf(var + EPS);
            sscale[tid] = sc;
            sshift[tid] = beta[tid] - mu * sc;
        }
        __syncthreads();
    }

    const int NCHUNK = K / KC;
    for (int kc = 0; kc < NCHUNK; kc++) {
        int k0 = kc * KC;
#pragma unroll
        for (int it = 0; it < 2; it++) {
            int idx = tid + it * 256;
            int r = idx >> 2, c4 = idx & 3;
            float4 v = ra[it];
            if (TRANSFORM) {
                int kb = k0 + c4 * 4;
                v.x = fmaxf(v.x * sscale[kb + 0] + sshift[kb + 0], 0.f);
                v.y = fmaxf(v.y * sscale[kb + 1] + sshift[kb + 1], 0.f);
                v.z = fmaxf(v.z * sscale[kb + 2] + sshift[kb + 2], 0.f);
                v.w = fmaxf(v.w * sscale[kb + 3] + sshift[kb + 3], 0.f);
            }
            __nv_bfloat162 h0, l0, h1, l1;
            bf16_split2(v.x, v.y, h0, l0);
            bf16_split2(v.z, v.w, h1, l1);
            Ah2[c4 * 2 + 0][r] = h0; Al2[c4 * 2 + 0][r] = l0;
            Ah2[c4 * 2 + 1][r] = h1; Al2[c4 * 2 + 1][r] = l1;
        }
        if (bAct) {
            const float* pe = (const float*)&rbE;
            const float* po = (const float*)&rbO;
#pragma unroll
            for (int j = 0; j < 4; j++) {
                __nv_bfloat162 h, l;
                bf16_split2(pe[j], po[j], h, l);
                Bh2[bk2][bn4 * 4 + j] = h;
                Bl2[bk2][bn4 * 4 + j] = l;
            }
        }
        __syncthreads();
        if (kc + 1 < NCHUNK) {
            int kn = k0 + KC;
#pragma unroll
            for (int it = 0; it < 2; it++) {
                int idx = tid + it * 256;
                int r = idx >> 2, c4 = idx & 3;
                ra[it] = loadA(rowBase + r, kn + c4 * 4);
            }
            if (bAct) {
                rbE = *(const float4*)(B + (size_t)(kn + bk2 * 2) * BN + bn4 * 4);
                rbO = *(const float4*)(B + (size_t)(kn + bk2 * 2 + 1) * BN + bn4 * 4);
            }
        }
        uint32_t ahi[2][4], alo[2][4];
#pragma unroll
        for (int mt = 0; mt < 2; mt++) {
            int rb0 = wrow + mt * 16 + r8;
            ahi[mt][0] = *(const uint32_t*)&Ah2[q][rb0];
            ahi[mt][1] = *(const uint32_t*)&Ah2[q][rb0 + 8];
            ahi[mt][2] = *(const uint32_t*)&Ah2[q + 4][rb0];
            ahi[mt][3] = *(const uint32_t*)&Ah2[q + 4][rb0 + 8];
            alo[mt][0] = *(const uint32_t*)&Al2[q][rb0];
            alo[mt][1] = *(const uint32_t*)&Al2[q][rb0 + 8];
            alo[mt][2] = *(const uint32_t*)&Al2[q + 4][rb0];
            alo[mt][3] = *(const uint32_t*)&Al2[q + 4][rb0 + 8];
        }
#pragma unroll
        for (int nt = 0; nt < NT; nt++) {
            int cb = wcol + nt * 8 + r8;
            uint32_t bh0 = *(const uint32_t*)&Bh2[q][cb];
            uint32_t bh1 = *(const uint32_t*)&Bh2[q + 4][cb];
            uint32_t bl0 = *(const uint32_t*)&Bl2[q][cb];
            uint32_t bl1 = *(const uint32_t*)&Bl2[q + 4][cb];
            mma_bf16(acc[0][nt], ahi[0], bh0, bh1);
            mma_bf16(acc[1][nt], ahi[1], bh0, bh1);
            mma_bf16(acc[0][nt], alo[0], bh0, bh1);
            mma_bf16(acc[1][nt], alo[1], bh0, bh1);
            mma_bf16(acc[0][nt], ahi[0], bl0, bl1);
            mma_bf16(acc[1][nt], ahi[1], bl0, bl1);
        }
        __syncthreads();
    }

    // ---- epilogue: store fp16 C + fused per-row s,d (2-warp combine) ----
    float asr[2 * NT], adr[2 * NT];
#pragma unroll
    for (int nt = 0; nt < NT; nt++) {
        int col = wcol + nt * 8 + q * 2;
        asr[2 * nt] = a_s[col];     asr[2 * nt + 1] = a_s[col + 1];
        adr[2 * nt] = a_d[col];     adr[2 * nt + 1] = a_d[col + 1];
    }
    float spA[4], dpA[4];
#pragma unroll
    for (int mt = 0; mt < 2; mt++) {
#pragma unroll
        for (int rh = 0; rh < 2; rh++) {
            int row = rowBase + wrow + mt * 16 + rh * 8 + r8;
            float sp = 0.f, dp = 0.f;
#pragma unroll
            for (int nt = 0; nt < NT; nt++) {
                float c0 = acc[mt][nt][rh * 2 + 0];
                float c1 = acc[mt][nt][rh * 2 + 1];
                sp += c0 * asr[2 * nt] + c1 * asr[2 * nt + 1];
                dp += c0 * adr[2 * nt] + c1 * adr[2 * nt + 1];
                if (row < M) {
                    int col = wcol + nt * 8 + q * 2;
                    __half2 hv = __floats2half2_rn(c0, c1);
                    *(uint32_t*)(C + (size_t)row * BN + col) = *(uint32_t*)&hv;
                }
            }
            sp += __shfl_xor_sync(0xFFFFFFFFu, sp, 1);
            sp += __shfl_xor_sync(0xFFFFFFFFu, sp, 2);
            dp += __shfl_xor_sync(0xFFFFFFFFu, dp, 1);
            dp += __shfl_xor_sync(0xFFFFFFFFu, dp, 2);
            spA[mt * 2 + rh] = sp;
            dpA[mt * 2 + rh] = dp;
        }
    }
    if (warpCol == 0 && q == 0) {
#pragma unroll
        for (int i = 0; i < 4; i++) {
            int lr = wrow + (i >> 1) * 16 + (i & 1) * 8 + r8;
            sS[lr] = spA[i];
            sD[lr] = dpA[i];
        }
    }
    __syncthreads();
    if (warpCol == 1 && q == 0) {
#pragma unroll
        for (int i = 0; i < 4; i++) {
            int lr = wrow + (i >> 1) * 16 + (i & 1) * 8 + r8;
            int row = rowBase + lr;
            if (row < M) {
                so[row] = spA[i] + sS[lr];
                dout[row] = dpA[i] + sD[lr];
            }
        }
    }
}

// ------------------------------ CSR build --------------------------------
__global__ void hist_kernel(int E_, int n, const int* __restrict__ ei,
                            int* __restrict__ deg) {
    int e = blockIdx.x * blockDim.x + threadIdx.x;
    int tot = E_ + n;
    if (e >= tot) return;
    int dst = (e < E_) ? ei[E_ + e] : (e - E_);
    atomicAdd(&deg[dst], 1);
}

__global__ void scan1_kernel(const int* __restrict__ deg, int* __restrict__ excl,
                             int* __restrict__ bsums, int n) {
    __shared__ int sh[256];
    int tid = threadIdx.x;
    int base = blockIdx.x * 1024 + tid * 4;
    int v[4];
#pragma unroll
    for (int j = 0; j < 4; j++) v[j] = (base + j < n) ? deg[base + j] : 0;
    int tsum = v[0] + v[1] + v[2] + v[3];
    sh[tid] = tsum;
    __syncthreads();
    for (int off = 1; off < 256; off <<= 1) {
        int t = (tid >= off) ? sh[tid - off] : 0;
        __syncthreads();
        sh[tid] += t;
        __syncthreads();
    }
    int run = sh[tid] - tsum;
#pragma unroll
    for (int j = 0; j < 4; j++) {
        if (base + j < n) excl[base + j] = run;
        run += v[j];
    }
    if (tid == 255) bsums[blockIdx.x] = sh[255];
}

// parallel exclusive scan of <=256 block sums; also zeroes both BN stat
// buffers (folds two memset nodes into this launch).
__global__ void scan2_kernel(int* __restrict__ bsums, int nb,
                             float* __restrict__ st0, float* __restrict__ st1) {
    __shared__ int sh[256];
    int tid = threadIdx.x;
    st0[tid] = 0.f;
    st1[tid] = 0.f;
    int v = (tid < nb) ? bsums[tid] : 0;
    sh[tid] = v;
    __syncthreads();
    for (int off = 1; off < 256; off <<= 1) {
        int t = (tid >= off) ? sh[tid - off] : 0;
        __syncthreads();
        sh[tid] += t;
        __syncthreads();
    }
    if (tid < nb) bsums[tid] = sh[tid] - v;
}

__global__ void scan3_kernel(int* __restrict__ rowptr, int* __restrict__ cursor,
                             const int* __restrict__ bsums, int n, int tot) {
    int i = blockIdx.x * blockDim.x + threadIdx.x;
    if (i < n) {
        int v = rowptr[i] + bsums[i >> 10];
        rowptr[i] = v;
        cursor[i] = v;
    }
    if (i == 0) rowptr[n] = tot;
}

__global__ void fill_kernel(int E_, int n, const int* __restrict__ ei,
                            int* __restrict__ cursor, int* __restrict__ csrc) {
    int e = blockIdx.x * blockDim.x + threadIdx.x;
    int tot = E_ + n;
    if (e >= tot) return;
    int src, dst;
    if (e < E_) { src = ei[e]; dst = ei[E_ + e]; }
    else        { src = dst = e - E_; }
    int pos = atomicAdd(&cursor[dst], 1);
    csrc[pos] = src;
}

// ---------- single-pass softmax + aggregation -----------------------------
// D=128: half-warp per edge. D=64: quarter-warp per edge. Feature gather is
// depth-2 software-pipelined (two uint4 in flight per sub-group) to cover L2
// latency. OUTH: write fp16 (layer 0) or fp32 (final output).
template <int D, bool OUTH>
__global__ __launch_bounds__(256) void gat_agg_kernel(
    int n, const int* __restrict__ rowptr,
    const int* __restrict__ csrc,
    const float* __restrict__ s,
    const float* __restrict__ dd,
    const __half* __restrict__ Hm,
    void* __restrict__ outp) {
    constexpr int LPE = (D == 128) ? 16 : 8;
    constexpr int EPI = 32 / LPE;
    constexpr int FL = D / LPE;       // 8 for both
    constexpr int AP = FL / 2;        // 4
    int w = (blockIdx.x * blockDim.x + threadIdx.x) >> 5;
    int lane = threadIdx.x & 31;
    if (w >= n) return;
    int start = rowptr[w];
    int end = rowptr[w + 1];
    float dv = dd[w];
    int hl = lane & (LPE - 1);
    int sub = lane / LPE;

    float den = 0.f;
    uint64_t acc[AP];
#pragma unroll
    for (int j = 0; j < AP; j++) acc[j] = 0ull;

    for (int base = start; base < end; base += 32) {
        int i = base + lane;
        int srcv = 0;
        float wv = 0.f;
        if (i < end) {
            srcv = csrc[i];
            float lg = s[srcv] + dv;
            lg = lg > 0.f ? lg : 0.2f * lg;
            wv = __expf(lg);
        }
        den += wv;
        int cnt = min(32, end - base);
        // ---- depth-2 pipelined gather ----
        float c0 = __shfl_sync(0xFFFFFFFFu, wv, sub);
        int   s0 = __shfl_sync(0xFFFFFFFFu, srcv, sub);
        uint4 u0 = *(const uint4*)(Hm + (size_t)s0 * D + hl * 8);
        float c1 = __shfl_sync(0xFFFFFFFFu, wv, EPI + sub);
        int   s1 = __shfl_sync(0xFFFFFFFFu, srcv, EPI + sub);
        uint4 u1 = *(const uint4*)(Hm + (size_t)s1 * D + hl * 8);
        for (int k = 0; k < cnt; k += EPI) {
            float c = c0; uint4 u = u0;
            c0 = c1; u0 = u1;
            int kn = k + 2 * EPI;
            if (kn < 32) {
                c1 = __shfl_sync(0xFFFFFFFFu, wv, kn + sub);
                int sn = __shfl_sync(0xFFFFFFFFu, srcv, kn + sub);
                u1 = *(const uint4*)(Hm + (size_t)sn * D + hl * 8);
            }
            uint64_t cd = dup2(c);
            float2 f0 = __half22float2(*(const __half2*)&u.x);
            float2 f1 = __half22float2(*(const __half2*)&u.y);
            float2 f2 = __half22float2(*(const __half2*)&u.z);
            float2 f3 = __half22float2(*(const __half2*)&u.w);
            fma2(acc[0], cd, pack2(f0.x, f0.y));
            fma2(acc[1], cd, pack2(f1.x, f1.y));
            fma2(acc[2], cd, pack2(f2.x, f2.y));
            fma2(acc[3], cd, pack2(f3.x, f3.y));
        }
    }
#pragma unroll
    for (int o = 16; o; o >>= 1)
        den += __shfl_xor_sync(0xFFFFFFFFu, den, o);
    float inv = 1.f / den;

    float f[FL];
#pragma unroll
    for (int j = 0; j < AP; j++) {
        float2 a = unpack2(acc[j]);
        f[2 * j] = a.x;
        f[2 * j + 1] = a.y;
    }
#pragma unroll
    for (int j = 0; j < FL; j++) {
        f[j] += __shfl_xor_sync(0xFFFFFFFFu, f[j], 16);
        if (D == 64) f[j] += __shfl_xor_sync(0xFFFFFFFFu, f[j], 8);
        f[j] *= inv;
    }
    if (lane < LPE) {
        if (OUTH) {
            __half2 hv[AP];
#pragma unroll
            for (int j = 0; j < AP; j++)
                hv[j] = __floats2half2_rn(f[2 * j], f[2 * j + 1]);
            *(uint4*)((__half*)outp + (size_t)w * D + hl * FL) = *(uint4*)hv;
        } else {
            float* op = (float*)outp + (size_t)w * D + hl * FL;
            *(float4*)op = make_float4(f[0], f[1], f[2], f[3]);
            *(float4*)(op + 4) = make_float4(f[4], f[5], f[6], f[7]);
        }
    }
}

// ---------------------------- BatchNorm ----------------------------------
__global__ void bn_stats_half_kernel(int n, const __half* __restrict__ x,
                                     float* __restrict__ stats) {
    int c = threadIdx.x;   // blockDim.x == 128
    int r0 = blockIdx.x * 64;
    int r1 = min(r0 + 64, n);
    float s = 0.f, q = 0.f;
    for (int r = r0; r < r1; r++) {
        float v = __half2float(x[(size_t)r * 128 + c]);
        s += v;
        q += v * v;
    }
    atomicAdd(&stats[c], s);
    atomicAdd(&stats[128 + c], q);
}

template <int D>
__global__ void bn_stats_kernel(int n, const float* __restrict__ x,
                                float* __restrict__ stats) {
    int c = threadIdx.x;
    int r0 = blockIdx.x * 64;
    int r1 = min(r0 + 64, n);
    float s = 0.f, q = 0.f;
    for (int r = r0; r < r1; r++) {
        float v = x[(size_t)r * D + c];
        s += v;
        q += v * v;
    }
    atomicAdd(&stats[c], s);
    atomicAdd(&stats[128 + c], q);
}

template <int D>
__global__ void bn_apply_kernel(int n, float* __restrict__ x,
                                const float* __restrict__ stats,
                                const float* __restrict__ gamma,
                                const float* __restrict__ beta) {
    int i = blockIdx.x * blockDim.x + threadIdx.x;
    if (i >= n * D) return;
    int c = i % D;
    float invn = 1.f / (float)n;
    float mu = stats[c] * invn;
    float var = stats[128 + c] * invn - mu * mu;
    float sc = gamma[c] * rsqrtf(var + EPS);
    x[i] = fmaxf((x[i] - mu) * sc + beta[c], 0.f);
}

// ------------------------------ launcher ---------------------------------
extern "C" void kernel_launch(void* const* d_in, const int* in_sizes, int n_in,
                              void* d_out, int out_size) {
    const float* x   = (const float*)d_in[0];
    const int*   ei  = (const int*)d_in[1];
    const float* W0  = (const float*)d_in[2];
    const float* as0 = (const float*)d_in[3];
    const float* ad0 = (const float*)d_in[4];
    const float* gg0 = (const float*)d_in[5];
    const float* bb0 = (const float*)d_in[6];
    const float* W1  = (const float*)d_in[7];
    const float* as1 = (const float*)d_in[8];
    const float* ad1 = (const float*)d_in[9];
    const float* gg1 = (const float*)d_in[10];
    const float* bb1 = (const float*)d_in[11];

    const int F = 128, Hd = 128, C = 64;
    const int n  = in_sizes[0] / F;
    const int E_ = in_sizes[1] / 2;
    const int tot = E_ + n;
    float* out = (float*)d_out;

    float *sbuf, *dbuf, *stat0, *stat1;
    __half *hbuf, *abuf;
    int *degb, *rowp, *curs, *csrc, *bsums;
    cudaGetSymbolAddress((void**)&hbuf, g_h);
    cudaGetSymbolAddress((void**)&abuf, g_aggh);
    cudaGetSymbolAddress((void**)&sbuf, g_s);
    cudaGetSymbolAddress((void**)&dbuf, g_d);
    cudaGetSymbolAddress((void**)&stat0, g_stats0);
    cudaGetSymbolAddress((void**)&stat1, g_stats1);
    cudaGetSymbolAddress((void**)&degb, g_deg);
    cudaGetSymbolAddress((void**)&rowp, g_rowptr);
    cudaGetSymbolAddress((void**)&curs, g_cursor);
    cudaGetSymbolAddress((void**)&csrc, g_csrc);
    cudaGetSymbolAddress((void**)&bsums, g_bsums);

    static cudaStream_t s2 = nullptr;
    static cudaEvent_t evFork = nullptr, evJoin = nullptr;
    if (s2 == nullptr) {
        cudaStreamCreateWithFlags(&s2, cudaStreamNonBlocking);
        cudaEventCreateWithFlags(&evFork, cudaEventDisableTiming);
        cudaEventCreateWithFlags(&evJoin, cudaEventDisableTiming);
    }

    // ============== fork: CSR build + stat zeroing on s2 ==================
    cudaEventRecord(evFork, 0);
    cudaStreamWaitEvent(s2, evFork, 0);

    cudaMemsetAsync(degb, 0, (size_t)n * sizeof(int), s2);
    hist_kernel<<<(tot + 255) / 256, 256, 0, s2>>>(E_, n, ei, degb);
    int nb = (n + 1023) / 1024;
    scan1_kernel<<<nb, 256, 0, s2>>>(degb, rowp, bsums, n);
    scan2_kernel<<<1, 256, 0, s2>>>(bsums, nb, stat0, stat1);
    scan3_kernel<<<(n + 255) / 256, 256, 0, s2>>>(rowp, curs, bsums, n, tot);
    fill_kernel<<<(tot + 255) / 256, 256, 0, s2>>>(E_, n, ei, curs, csrc);
    cudaEventRecord(evJoin, s2);

    // ============================ Layer 0 =================================
    gemm_mma_kernel<128, false, false><<<(n + 127) / 128, 256>>>(
        n, F, x, W0, hbuf, as0, ad0, sbuf, dbuf, nullptr, nullptr, nullptr);

    cudaStreamWaitEvent(0, evJoin, 0);
    gat_agg_kernel<128, true><<<(n * 32 + 255) / 256, 256>>>(
        n, rowp, csrc, sbuf, dbuf, hbuf, abuf);
    bn_stats_half_kernel<<<(n + 63) / 64, 128>>>(n, abuf, stat0);

    // ============================ Layer 1 =================================
    gemm_mma_kernel<64, true, true><<<(n + 127) / 128, 256>>>(
        n, Hd, abuf, W1, hbuf, as1, ad1, sbuf, dbuf, stat0, gg0, bb0);
    gat_agg_kernel<64, false><<<(n * 32 + 255) / 256, 256>>>(
        n, rowp, csrc, sbuf, dbuf, hbuf, out);
    bn_stats_kernel<64><<<(n + 63) / 64, 64>>>(n, out, stat1);
    bn_apply_kernel<64><<<((long long)n * C + 255) / 256, 256>>>(n, out, stat1, gg1, bb1);
}

// round 16
// speedup vs baseline: 1.0469x; 1.0469x over previous
#include <cuda_runtime.h>
#include <cuda_fp16.h>
#include <cuda_bf16.h>
#include <cstdint>

#define NMAX 100000
#define EMAX 1700000
#define EPS 1e-5f

// -------- scratch (static device globals; no allocation allowed) --------
__device__ __half g_h[(size_t)NMAX * 128];    // GEMM output h (fp16)
__device__ __half g_aggh[(size_t)NMAX * 128]; // layer-0 aggregation (fp16)
__device__ float g_s[NMAX];
__device__ float g_d[NMAX];
__device__ int   g_deg[NMAX];
__device__ int   g_rowptr[NMAX + 1];
__device__ int   g_cursor[NMAX];
__device__ int   g_csrc[EMAX];
__device__ int   g_bsums[256];
__device__ float g_stats0[256];
__device__ float g_stats1[256];

// ---------------------- packed f32x2 helpers ------------------------------
__device__ __forceinline__ void fma2(uint64_t& d, uint64_t a, uint64_t b) {
    asm("fma.rn.f32x2 %0, %1, %2, %3;" : "=l"(d) : "l"(a), "l"(b), "l"(d));
}
__device__ __forceinline__ uint64_t dup2(float x) {
    uint64_t r;
    asm("mov.b64 %0, {%1, %1};" : "=l"(r) : "f"(x));
    return r;
}
__device__ __forceinline__ uint64_t pack2(float x, float y) {
    uint64_t r;
    asm("mov.b64 %0, {%1, %2};" : "=l"(r) : "f"(x), "f"(y));
    return r;
}
__device__ __forceinline__ float2 unpack2(uint64_t v) {
    float2 f;
    asm("mov.b64 {%0, %1}, %2;" : "=f"(f.x), "=f"(f.y) : "l"(v));
    return f;
}

// ---------------------- bf16 split + mma helpers --------------------------
__device__ __forceinline__ void bf16_split2(float x, float y,
                                            __nv_bfloat162& hi,
                                            __nv_bfloat162& lo) {
    __nv_bfloat16 hx = __float2bfloat16_rn(x);
    __nv_bfloat16 hy = __float2bfloat16_rn(y);
    hi.x = hx; hi.y = hy;
    lo.x = __float2bfloat16_rn(x - __bfloat162float(hx));
    lo.y = __float2bfloat16_rn(y - __bfloat162float(hy));
}
// m16n8k16 bf16 MMA, fp32 accumulate (baseline PTX, sm_80+)
__device__ __forceinline__ void mma_bf16(float* c, const uint32_t* a,
                                         uint32_t b0, uint32_t b1) {
    asm("mma.sync.aligned.m16n8k16.row.col.f32.bf16.bf16.f32 "
        "{%0,%1,%2,%3}, {%4,%5,%6,%7}, {%8,%9}, {%0,%1,%2,%3};"
        : "+f"(c[0]), "+f"(c[1]), "+f"(c[2]), "+f"(c[3])
        : "r"(a[0]), "r"(a[1]), "r"(a[2]), "r"(a[3]), "r"(b0), "r"(b1));
}

// --------------------- split-bf16 tensor-core GEMM ------------------------
// AHALF: A is fp16 (8-byte loads per 4 elems); else fp32 (16-byte loads).
template <int BN, bool TRANSFORM, bool AHALF>
__global__ __launch_bounds__(256) void gemm_mma_kernel(
    int M, int K,
    const void* __restrict__ Ap,
    const float* __restrict__ B,
    __half* __restrict__ C,
    const float* __restrict__ a_s,
    const float* __restrict__ a_d,
    float* __restrict__ so, float* __restrict__ dout,
    const float* __restrict__ stats,
    const float* __restrict__ gamma,
    const float* __restrict__ beta) {
    constexpr int KC = 16;
    constexpr int K2 = KC / 2;
    constexpr int NT = BN / 16;
    __shared__ __nv_bfloat162 Ah2[K2][136], Al2[K2][136];
    __shared__ __nv_bfloat162 Bh2[K2][BN + 8], Bl2[K2][BN + 8];
    __shared__ float sscale[128], sshift[128];
    __shared__ float sS[128], sD[128];

    const int tid = threadIdx.x;
    const int warp = tid >> 5;
    const int lane = tid & 31;
    const int q = lane & 3;
    const int r8 = lane >> 2;
    const int warpRow = warp & 3;
    const int warpCol = warp >> 2;
    const int rowBase = blockIdx.x * 128;
    const int wrow = warpRow * 32;
    const int wcol = warpCol * (BN / 2);

    float acc[2][NT][4];
#pragma unroll
    for (int mt = 0; mt < 2; mt++)
#pragma unroll
        for (int nt = 0; nt < NT; nt++)
#pragma unroll
            for (int j = 0; j < 4; j++) acc[mt][nt][j] = 0.f;

    auto loadA = [&](int gr, int kb) -> float4 {
        if (gr >= M) return make_float4(0.f, 0.f, 0.f, 0.f);
        if (AHALF) {
            uint2 u = *(const uint2*)((const __half*)Ap + (size_t)gr * K + kb);
            float2 p0 = __half22float2(*(const __half2*)&u.x);
            float2 p1 = __half22float2(*(const __half2*)&u.y);
            return make_float4(p0.x, p0.y, p1.x, p1.y);
        } else {
            return *(const float4*)((const float*)Ap + (size_t)gr * K + kb);
        }
    };

    float4 ra[2];
    float4 rbE, rbO;
    const int bk2 = (BN == 128) ? (tid >> 5) : (tid >> 4);
    const int bn4 = (BN == 128) ? (tid & 31) : (tid & 15);
    const bool bAct = (BN == 128) || (tid < 128);

#pragma unroll
    for (int it = 0; it < 2; it++) {
        int idx = tid + it * 256;
        int r = idx >> 2, c4 = idx & 3;
        ra[it] = loadA(rowBase + r, c4 * 4);
    }
    if (bAct) {
        rbE = *(const float4*)(B + (size_t)(bk2 * 2) * BN + bn4 * 4);
        rbO = *(const float4*)(B + (size_t)(bk2 * 2 + 1) * BN + bn4 * 4);
    }

    if (TRANSFORM) {
        if (tid < K) {
            float invn = 1.f / (float)M;
            float mu = stats[tid] * invn;
            float var = stats[128 + tid] * invn - mu * mu;
            float sc = gamma[tid] * rsqrtf(var + EPS);
            sscale[tid] = sc;
            sshift[tid] = beta[tid] - mu * sc;
        }
        __syncthreads();
    }

    const int NCHUNK = K / KC;
    for (int kc = 0; kc < NCHUNK; kc++) {
        int k0 = kc * KC;
#pragma unroll
        for (int it = 0; it < 2; it++) {
            int idx = tid + it * 256;
            int r = idx >> 2, c4 = idx & 3;
            float4 v = ra[it];
            if (TRANSFORM) {
                int kb = k0 + c4 * 4;
                v.x = fmaxf(v.x * sscale[kb + 0] + sshift[kb + 0], 0.f);
                v.y = fmaxf(v.y * sscale[kb + 1] + sshift[kb + 1], 0.f);
                v.z = fmaxf(v.z * sscale[kb + 2] + sshift[kb + 2], 0.f);
                v.w = fmaxf(v.w * sscale[kb + 3] + sshift[kb + 3], 0.f);
            }
            __nv_bfloat162 h0, l0, h1, l1;
            bf16_split2(v.x, v.y, h0, l0);
            bf16_split2(v.z, v.w, h1, l1);
            Ah2[c4 * 2 + 0][r] = h0; Al2[c4 * 2 + 0][r] = l0;
            Ah2[c4 * 2 + 1][r] = h1; Al2[c4 * 2 + 1][r] = l1;
        }
        if (bAct) {
            const float* pe = (const float*)&rbE;
            const float* po = (const float*)&rbO;
#pragma unroll
            for (int j = 0; j < 4; j++) {
                __nv_bfloat162 h, l;
                bf16_split2(pe[j], po[j], h, l);
                Bh2[bk2][bn4 * 4 + j] = h;
                Bl2[bk2][bn4 * 4 + j] = l;
            }
        }
        __syncthreads();
        if (kc + 1 < NCHUNK) {
            int kn = k0 + KC;
#pragma unroll
            for (int it = 0; it < 2; it++) {
                int idx = tid + it * 256;
                int r = idx >> 2, c4 = idx & 3;
                ra[it] = loadA(rowBase + r, kn + c4 * 4);
            }
            if (bAct) {
                rbE = *(const float4*)(B + (size_t)(kn + bk2 * 2) * BN + bn4 * 4);
                rbO = *(const float4*)(B + (size_t)(kn + bk2 * 2 + 1) * BN + bn4 * 4);
            }
        }
        uint32_t ahi[2][4], alo[2][4];
#pragma unroll
        for (int mt = 0; mt < 2; mt++) {
            int rb0 = wrow + mt * 16 + r8;
            ahi[mt][0] = *(const uint32_t*)&Ah2[q][rb0];
            ahi[mt][1] = *(const uint32_t*)&Ah2[q][rb0 + 8];
            ahi[mt][2] = *(const uint32_t*)&Ah2[q + 4][rb0];
            ahi[mt][3] = *(const uint32_t*)&Ah2[q + 4][rb0 + 8];
            alo[mt][0] = *(const uint32_t*)&Al2[q][rb0];
            alo[mt][1] = *(const uint32_t*)&Al2[q][rb0 + 8];
            alo[mt][2] = *(const uint32_t*)&Al2[q + 4][rb0];
            alo[mt][3] = *(const uint32_t*)&Al2[q + 4][rb0 + 8];
        }
#pragma unroll
        for (int nt = 0; nt < NT; nt++) {
            int cb = wcol + nt * 8 + r8;
            uint32_t bh0 = *(const uint32_t*)&Bh2[q][cb];
            uint32_t bh1 = *(const uint32_t*)&Bh2[q + 4][cb];
            uint32_t bl0 = *(const uint32_t*)&Bl2[q][cb];
            uint32_t bl1 = *(const uint32_t*)&Bl2[q + 4][cb];
            mma_bf16(acc[0][nt], ahi[0], bh0, bh1);
            mma_bf16(acc[1][nt], ahi[1], bh0, bh1);
            mma_bf16(acc[0][nt], alo[0], bh0, bh1);
            mma_bf16(acc[1][nt], alo[1], bh0, bh1);
            mma_bf16(acc[0][nt], ahi[0], bl0, bl1);
            mma_bf16(acc[1][nt], ahi[1], bl0, bl1);
        }
        __syncthreads();
    }

    // ---- epilogue: store fp16 C + fused per-row s,d (2-warp combine) ----
    float asr[2 * NT], adr[2 * NT];
#pragma unroll
    for (int nt = 0; nt < NT; nt++) {
        int col = wcol + nt * 8 + q * 2;
        asr[2 * nt] = a_s[col];     asr[2 * nt + 1] = a_s[col + 1];
        adr[2 * nt] = a_d[col];     adr[2 * nt + 1] = a_d[col + 1];
    }
    float spA[4], dpA[4];
#pragma unroll
    for (int mt = 0; mt < 2; mt++) {
#pragma unroll
        for (int rh = 0; rh < 2; rh++) {
            int row = rowBase + wrow + mt * 16 + rh * 8 + r8;
            float sp = 0.f, dp = 0.f;
#pragma unroll
            for (int nt = 0; nt < NT; nt++) {
                float c0 = acc[mt][nt][rh * 2 + 0];
                float c1 = acc[mt][nt][rh * 2 + 1];
                sp += c0 * asr[2 * nt] + c1 * asr[2 * nt + 1];
                dp += c0 * adr[2 * nt] + c1 * adr[2 * nt + 1];
                if (row < M) {
                    int col = wcol + nt * 8 + q * 2;
                    __half2 hv = __floats2half2_rn(c0, c1);
                    *(uint32_t*)(C + (size_t)row * BN + col) = *(uint32_t*)&hv;
                }
            }
            sp += __shfl_xor_sync(0xFFFFFFFFu, sp, 1);
            sp += __shfl_xor_sync(0xFFFFFFFFu, sp, 2);
            dp += __shfl_xor_sync(0xFFFFFFFFu, dp, 1);
            dp += __shfl_xor_sync(0xFFFFFFFFu, dp, 2);
            spA[mt * 2 + rh] = sp;
            dpA[mt * 2 + rh] = dp;
        }
    }
    if (warpCol == 0 && q == 0) {
#pragma unroll
        for (int i = 0; i < 4; i++) {
            int lr = wrow + (i >> 1) * 16 + (i & 1) * 8 + r8;
            sS[lr] = spA[i];
            sD[lr] = dpA[i];
        }
    }
    __syncthreads();
    if (warpCol == 1 && q == 0) {
#pragma unroll
        for (int i = 0; i < 4; i++) {
            int lr = wrow + (i >> 1) * 16 + (i & 1) * 8 + r8;
            int row = rowBase + lr;
            if (row < M) {
                so[row] = spA[i] + sS[lr];
                dout[row] = dpA[i] + sD[lr];
            }
        }
    }
}

// ------------------------------ CSR build --------------------------------
__global__ void hist_kernel(int E_, int n, const int* __restrict__ ei,
                            int* __restrict__ deg) {
    int e = blockIdx.x * blockDim.x + threadIdx.x;
    int tot = E_ + n;
    if (e >= tot) return;
    int dst = (e < E_) ? ei[E_ + e] : (e - E_);
    atomicAdd(&deg[dst], 1);
}

__global__ void scan1_kernel(const int* __restrict__ deg, int* __restrict__ excl,
                             int* __restrict__ bsums, int n) {
    __shared__ int sh[256];
    int tid = threadIdx.x;
    int base = blockIdx.x * 1024 + tid * 4;
    int v[4];
#pragma unroll
    for (int j = 0; j < 4; j++) v[j] = (base + j < n) ? deg[base + j] : 0;
    int tsum = v[0] + v[1] + v[2] + v[3];
    sh[tid] = tsum;
    __syncthreads();
    for (int off = 1; off < 256; off <<= 1) {
        int t = (tid >= off) ? sh[tid - off] : 0;
        __syncthreads();
        sh[tid] += t;
        __syncthreads();
    }
    int run = sh[tid] - tsum;
#pragma unroll
    for (int j = 0; j < 4; j++) {
        if (base + j < n) excl[base + j] = run;
        run += v[j];
    }
    if (tid == 255) bsums[blockIdx.x] = sh[255];
}

// parallel exclusive scan of <=256 block sums; also zeroes both BN stat
// buffers (folds two memset nodes into this launch).
__global__ void scan2_kernel(int* __restrict__ bsums, int nb,
                             float* __restrict__ st0, float* __restrict__ st1) {
    __shared__ int sh[256];
    int tid = threadIdx.x;
    st0[tid] = 0.f;
    st1[tid] = 0.f;
    int v = (tid < nb) ? bsums[tid] : 0;
    sh[tid] = v;
    __syncthreads();
    for (int off = 1; off < 256; off <<= 1) {
        int t = (tid >= off) ? sh[tid - off] : 0;
        __syncthreads();
        sh[tid] += t;
        __syncthreads();
    }
    if (tid < nb) bsums[tid] = sh[tid] - v;
}

__global__ void scan3_kernel(int* __restrict__ rowptr, int* __restrict__ cursor,
                             const int* __restrict__ bsums, int n, int tot) {
    int i = blockIdx.x * blockDim.x + threadIdx.x;
    if (i < n) {
        int v = rowptr[i] + bsums[i >> 10];
        rowptr[i] = v;
        cursor[i] = v;
    }
    if (i == 0) rowptr[n] = tot;
}

__global__ void fill_kernel(int E_, int n, const int* __restrict__ ei,
                            int* __restrict__ cursor, int* __restrict__ csrc) {
    int e = blockIdx.x * blockDim.x + threadIdx.x;
    int tot = E_ + n;
    if (e >= tot) return;
    int src, dst;
    if (e < E_) { src = ei[e]; dst = ei[E_ + e]; }
    else        { src = dst = e - E_; }
    int pos = atomicAdd(&cursor[dst], 1);
    csrc[pos] = src;
}

// ---------- single-pass softmax + aggregation -----------------------------
// 8 lanes per edge for both layers; each lane covers D/8 features.
// D=128: 2 independent uint4 loads per lane (32B). D=64: 1 uint4 (16B).
// 4 edges in flight per warp. Partials merged by shfl_xor(8,16).
template <int D, bool OUTH>
__global__ __launch_bounds__(256) void gat_agg_kernel(
    int n, const int* __restrict__ rowptr,
    const int* __restrict__ csrc,
    const float* __restrict__ s,
    const float* __restrict__ dd,
    const __half* __restrict__ Hm,
    void* __restrict__ outp) {
    constexpr int LPE = 8;            // lanes per edge
    constexpr int EPI = 4;            // edges per iteration
    constexpr int FL = D / LPE;       // 16 (D=128) or 8 (D=64) fp32 per lane
    constexpr int AP = FL / 2;        // packed accumulators (8 or 4)
    constexpr int NLD = D / 64;       // uint4 loads per lane (2 or 1)
    int w = (blockIdx.x * blockDim.x + threadIdx.x) >> 5;
    int lane = threadIdx.x & 31;
    if (w >= n) return;
    int start = rowptr[w];
    int end = rowptr[w + 1];
    float dv = dd[w];
    int hl = lane & (LPE - 1);
    int sub = lane >> 3;

    float den = 0.f;
    uint64_t acc[AP];
#pragma unroll
    for (int j = 0; j < AP; j++) acc[j] = 0ull;

    for (int base = start; base < end; base += 32) {
        int i = base + lane;
        int srcv = 0;
        float wv = 0.f;
        if (i < end) {
            srcv = csrc[i];
            float lg = s[srcv] + dv;
            lg = lg > 0.f ? lg : 0.2f * lg;
            wv = __expf(lg);
        }
        den += wv;
        int cnt = min(32, end - base);
        for (int k = 0; k < cnt; k += EPI) {
            int e = k + sub;                 // wv==0 for e>=cnt (OOB)
            float c = __shfl_sync(0xFFFFFFFFu, wv, e);
            int sc = __shfl_sync(0xFFFFFFFFu, srcv, e);
            uint64_t cd = dup2(c);
            const __half* rp = Hm + (size_t)sc * D + hl * (8 * NLD);
            uint4 u[NLD];
#pragma unroll
            for (int l = 0; l < NLD; l++) u[l] = ((const uint4*)rp)[l];
#pragma unroll
            for (int l = 0; l < NLD; l++) {
                float2 f0 = __half22float2(*(const __half2*)&u[l].x);
                float2 f1 = __half22float2(*(const __half2*)&u[l].y);
                float2 f2 = __half22float2(*(const __half2*)&u[l].z);
                float2 f3 = __half22float2(*(const __half2*)&u[l].w);
                fma2(acc[l * 4 + 0], cd, pack2(f0.x, f0.y));
                fma2(acc[l * 4 + 1], cd, pack2(f1.x, f1.y));
                fma2(acc[l * 4 + 2], cd, pack2(f2.x, f2.y));
                fma2(acc[l * 4 + 3], cd, pack2(f3.x, f3.y));
            }
        }
    }
#pragma unroll
    for (int o = 16; o; o >>= 1)
        den += __shfl_xor_sync(0xFFFFFFFFu, den, o);
    float inv = 1.f / den;

    float f[FL];
#pragma unroll
    for (int j = 0; j < AP; j++) {
        float2 a = unpack2(acc[j]);
        f[2 * j] = a.x;
        f[2 * j + 1] = a.y;
    }
#pragma unroll
    for (int j = 0; j < FL; j++) {
        f[j] += __shfl_xor_sync(0xFFFFFFFFu, f[j], 16);
        f[j] += __shfl_xor_sync(0xFFFFFFFFu, f[j], 8);
        f[j] *= inv;
    }
    if (lane < LPE) {
        if (OUTH) {
            __half2 hv[AP];
#pragma unroll
            for (int j = 0; j < AP; j++)
                hv[j] = __floats2half2_rn(f[2 * j], f[2 * j + 1]);
            __half* op = (__half*)outp + (size_t)w * D + hl * FL;
#pragma unroll
            for (int l = 0; l < NLD; l++)
                ((uint4*)op)[l] = ((uint4*)hv)[l];
        } else {
            float* op = (float*)outp + (size_t)w * D + hl * FL;
#pragma unroll
            for (int j = 0; j < FL; j += 4)
                *(float4*)(op + j) = make_float4(f[j], f[j + 1], f[j + 2], f[j + 3]);
        }
    }
}

// ---------------------------- BatchNorm ----------------------------------
__global__ void bn_stats_half_kernel(int n, const __half* __restrict__ x,
                                     float* __restrict__ stats) {
    int c = threadIdx.x;   // blockDim.x == 128
    int r0 = blockIdx.x * 64;
    int r1 = min(r0 + 64, n);
    float s = 0.f, q = 0.f;
    for (int r = r0; r < r1; r++) {
        float v = __half2float(x[(size_t)r * 128 + c]);
        s += v;
        q += v * v;
    }
    atomicAdd(&stats[c], s);
    atomicAdd(&stats[128 + c], q);
}

template <int D>
__global__ void bn_stats_kernel(int n, const float* __restrict__ x,
                                float* __restrict__ stats) {
    int c = threadIdx.x;
    int r0 = blockIdx.x * 64;
    int r1 = min(r0 + 64, n);
    float s = 0.f, q = 0.f;
    for (int r = r0; r < r1; r++) {
        float v = x[(size_t)r * D + c];
        s += v;
        q += v * v;
    }
    atomicAdd(&stats[c], s);
    atomicAdd(&stats[128 + c], q);
}

template <int D>
__global__ void bn_apply_kernel(int n, float* __restrict__ x,
                                const float* __restrict__ stats,
                                const float* __restrict__ gamma,
                                const float* __restrict__ beta) {
    int i = blockIdx.x * blockDim.x + threadIdx.x;
    if (i >= n * D) return;
    int c = i % D;
    float invn = 1.f / (float)n;
    float mu = stats[c] * invn;
    float var = stats[128 + c] * invn - mu * mu;
    float sc = gamma[c] * rsqrtf(var + EPS);
    x[i] = fmaxf((x[i] - mu) * sc + beta[c], 0.f);
}

// ------------------------------ launcher ---------------------------------
extern "C" void kernel_launch(void* const* d_in, const int* in_sizes, int n_in,
                              void* d_out, int out_size) {
    const float* x   = (const float*)d_in[0];
    const int*   ei  = (const int*)d_in[1];
    const float* W0  = (const float*)d_in[2];
    const float* as0 = (const float*)d_in[3];
    const float* ad0 = (const float*)d_in[4];
    const float* gg0 = (const float*)d_in[5];
    const float* bb0 = (const float*)d_in[6];
    const float* W1  = (const float*)d_in[7];
    const float* as1 = (const float*)d_in[8];
    const float* ad1 = (const float*)d_in[9];
    const float* gg1 = (const float*)d_in[10];
    const float* bb1 = (const float*)d_in[11];

    const int F = 128, Hd = 128, C = 64;
    const int n  = in_sizes[0] / F;
    const int E_ = in_sizes[1] / 2;
    const int tot = E_ + n;
    float* out = (float*)d_out;

    float *sbuf, *dbuf, *stat0, *stat1;
    __half *hbuf, *abuf;
    int *degb, *rowp, *curs, *csrc, *bsums;
    cudaGetSymbolAddress((void**)&hbuf, g_h);
    cudaGetSymbolAddress((void**)&abuf, g_aggh);
    cudaGetSymbolAddress((void**)&sbuf, g_s);
    cudaGetSymbolAddress((void**)&dbuf, g_d);
    cudaGetSymbolAddress((void**)&stat0, g_stats0);
    cudaGetSymbolAddress((void**)&stat1, g_stats1);
    cudaGetSymbolAddress((void**)&degb, g_deg);
    cudaGetSymbolAddress((void**)&rowp, g_rowptr);
    cudaGetSymbolAddress((void**)&curs, g_cursor);
    cudaGetSymbolAddress((void**)&csrc, g_csrc);
    cudaGetSymbolAddress((void**)&bsums, g_bsums);

    static cudaStream_t s2 = nullptr;
    static cudaEvent_t evFork = nullptr, evJoin = nullptr;
    if (s2 == nullptr) {
        cudaStreamCreateWithFlags(&s2, cudaStreamNonBlocking);
        cudaEventCreateWithFlags(&evFork, cudaEventDisableTiming);
        cudaEventCreateWithFlags(&evJoin, cudaEventDisableTiming);
    }

    // ============== fork: CSR build + stat zeroing on s2 ==================
    cudaEventRecord(evFork, 0);
    cudaStreamWaitEvent(s2, evFork, 0);

    cudaMemsetAsync(degb, 0, (size_t)n * sizeof(int), s2);
    hist_kernel<<<(tot + 255) / 256, 256, 0, s2>>>(E_, n, ei, degb);
    int nb = (n + 1023) / 1024;
    scan1_kernel<<<nb, 256, 0, s2>>>(degb, rowp, bsums, n);
    scan2_kernel<<<1, 256, 0, s2>>>(bsums, nb, stat0, stat1);
    scan3_kernel<<<(n + 255) / 256, 256, 0, s2>>>(rowp, curs, bsums, n, tot);
    fill_kernel<<<(tot + 255) / 256, 256, 0, s2>>>(E_, n, ei, curs, csrc);
    cudaEventRecord(evJoin, s2);

    // ============================ Layer 0 =================================
    gemm_mma_kernel<128, false, false><<<(n + 127) / 128, 256>>>(
        n, F, x, W0, hbuf, as0, ad0, sbuf, dbuf, nullptr, nullptr, nullptr);

    cudaStreamWaitEvent(0, evJoin, 0);
    gat_agg_kernel<128, true><<<(n * 32 + 255) / 256, 256>>>(
        n, rowp, csrc, sbuf, dbuf, hbuf, abuf);
    bn_stats_half_kernel<<<(n + 63) / 64, 128>>>(n, abuf, stat0);

    // ============================ Layer 1 =================================
    gemm_mma_kernel<64, true, true><<<(n + 127) / 128, 256>>>(
        n, Hd, abuf, W1, hbuf, as1, ad1, sbuf, dbuf, stat0, gg0, bb0);
    gat_agg_kernel<64, false><<<(n * 32 + 255) / 256, 256>>>(
        n, rowp, csrc, sbuf, dbuf, hbuf, out);
    bn_stats_kernel<64><<<(n + 63) / 64, 64>>>(n, out, stat1);
    bn_apply_kernel<64><<<((long long)n * C + 255) / 256, 256>>>(n, out, stat1, gg1, bb1);
}